// round 4
// baseline (speedup 1.0000x reference)
#include <cuda_runtime.h>
#include <math.h>

#define D 64
#define GMAX 256
#define N_MAX 100000
#define E_MAX 1200000
#define KC 8
#define BNEPS 1e-5f
#define BN_BLOCKS 512

// ------------------- scratch (static device globals; no allocation) -------------------
__device__ __align__(16) float d_h0[(size_t)N_MAX * D];
__device__ __align__(16) float d_ya[(size_t)N_MAX * D];
__device__ __align__(16) float d_yb[(size_t)N_MAX * D];
__device__ __align__(16) float d_p [(size_t)N_MAX * D];
__device__ float d_degw[N_MAX];
__device__ int   d_cnt[N_MAX];
__device__ int   d_fill[N_MAX];
__device__ int   d_rowstart[N_MAX];
__device__ int   d_blksum[64];
__device__ __align__(16) int2 d_edge[E_MAX];   // (src, attr bits) packed
__device__ int   d_gcount[GMAX];
__device__ int   d_goff[GMAX + 1];
__device__ double d_bnpart_s[BN_BLOCKS][D];
__device__ double d_bnpart_q[BN_BLOCKS][D];
__device__ __align__(16) float d_scale[3][D];
__device__ __align__(16) float d_shift[3][D];
__device__ float d_gpool[GMAX * D];

__device__ __forceinline__ float* nodebuf(int s) {
    switch (s) {
        case 0: return d_h0;
        case 1: return d_ya;
        default: return d_yb;
    }
}

// packed fp32x2 FMA (sm_100+): d = a*b + d per 32-bit lane, IEEE fp32 each
__device__ __forceinline__ void fma2(unsigned long long& d,
                                     unsigned long long a,
                                     unsigned long long b) {
    asm("fma.rn.f32x2 %0, %1, %2, %0;" : "+l"(d) : "l"(a), "l"(b));
}

// ------------------- init -------------------
__global__ void k_zero(int n) {
    int i = blockIdx.x * blockDim.x + threadIdx.x;
    if (i < n) { d_cnt[i] = 0; d_fill[i] = 0; d_degw[i] = 0.f; }
    if (i < GMAX) d_gcount[i] = 0;
}

// ------------------- embedding: h0 = x @ W_emb + b_emb -------------------
__global__ void k_embed(const float* __restrict__ x, const float* __restrict__ W,
                        const float* __restrict__ b, int n) {
    int i = blockIdx.x * blockDim.x + threadIdx.x;
    if (i >= n * D) return;
    int node = i >> 6, c = i & 63;
    float4 xr = *(const float4*)(x + (size_t)node * 4);
    float v = b[c];
    v = fmaf(xr.x, W[c], v);
    v = fmaf(xr.y, W[D + c], v);
    v = fmaf(xr.z, W[2 * D + c], v);
    v = fmaf(xr.w, W[3 * D + c], v);
    d_h0[i] = v;
}

// ------------------- CSR build (EdgeID int32, layout [2, E]) -------------------
__global__ void k_epass1(const int* __restrict__ eid, const float* __restrict__ attr, int E) {
    int e = blockIdx.x * blockDim.x + threadIdx.x;
    if (e >= E) return;
    int dd = eid[(size_t)E + e];
    atomicAdd(&d_cnt[dd], 1);
    atomicAdd(&d_degw[dd], attr[e]);
}

__global__ void k_scan1(int n) {
    __shared__ int sh[256];
    int t = threadIdx.x;
    int base = blockIdx.x * 4096 + t * 16;
    int v[16]; int tot = 0;
    #pragma unroll
    for (int i = 0; i < 16; i++) {
        int idx = base + i;
        v[i] = (idx < n) ? d_cnt[idx] : 0;
        tot += v[i];
    }
    sh[t] = tot; __syncthreads();
    for (int off = 1; off < 256; off <<= 1) {
        int add = (t >= off) ? sh[t - off] : 0;
        __syncthreads();
        sh[t] += add;
        __syncthreads();
    }
    int run = sh[t] - tot;
    #pragma unroll
    for (int i = 0; i < 16; i++) {
        int idx = base + i;
        if (idx < n) d_rowstart[idx] = run;
        run += v[i];
    }
    if (t == 255) d_blksum[blockIdx.x] = sh[255];
}

__global__ void k_scan2(int nb) {
    __shared__ int sh[256];
    int t = threadIdx.x;
    int v = (t < nb) ? d_blksum[t] : 0;
    sh[t] = v; __syncthreads();
    for (int off = 1; off < 256; off <<= 1) {
        int add = (t >= off) ? sh[t - off] : 0;
        __syncthreads();
        sh[t] += add;
        __syncthreads();
    }
    if (t < nb) d_blksum[t] = sh[t] - v;
}

__global__ void k_scan3(int n) {
    int i = blockIdx.x * blockDim.x + threadIdx.x;
    if (i < n) d_rowstart[i] += d_blksum[i >> 12];
}

__global__ void k_epass2(const int* __restrict__ eid, const float* __restrict__ attr, int E) {
    int e = blockIdx.x * blockDim.x + threadIdx.x;
    if (e >= E) return;
    int s  = eid[e];
    int dd = eid[(size_t)E + e];
    int pos = d_rowstart[dd] + atomicAdd(&d_fill[dd], 1);
    d_edge[pos] = make_int2(s, __float_as_int(attr[e]));
}

// ------------------- graph histogram + offsets -------------------
__global__ void k_ghist(const int* __restrict__ batch, int n) {
    int i = blockIdx.x * blockDim.x + threadIdx.x;
    if (i < n) atomicAdd(&d_gcount[batch[i]], 1);
}

__global__ void k_goff() {
    __shared__ int sh[GMAX];
    int t = threadIdx.x;
    int v = d_gcount[t];
    sh[t] = v; __syncthreads();
    for (int off = 1; off < GMAX; off <<= 1) {
        int add = (t >= off) ? sh[t - off] : 0;
        __syncthreads();
        sh[t] += add;
        __syncthreads();
    }
    d_goff[t + 1] = sh[t];
    if (t == 0) d_goff[0] = 0;
}

// ------------------- edge aggregation: p[i] = sum attr_e * hin[src_e] -------------------
// warp per node; unroll-4 for MLP=4 on the L2 gathers
template <bool APPLY>
__global__ void k_edge_agg(int insel, int slayer, int n) {
    int node = blockIdx.x * 8 + (threadIdx.x >> 5);
    if (node >= n) return;
    const float* __restrict__ in = nodebuf(insel);
    int lane = threadIdx.x & 31;
    int c0 = lane * 2;
    float sc0 = 1.f, sc1 = 1.f, sf0 = 0.f, sf1 = 0.f;
    if (APPLY) {
        sc0 = d_scale[slayer][c0];     sc1 = d_scale[slayer][c0 + 1];
        sf0 = d_shift[slayer][c0];     sf1 = d_shift[slayer][c0 + 1];
    }
    int rs = d_rowstart[node];
    int re = rs + d_cnt[node];
    float a0 = 0.f, a1 = 0.f;
    int j = rs;
    for (; j + 4 <= re; j += 4) {
        int2 e0 = d_edge[j];
        int2 e1 = d_edge[j + 1];
        int2 e2 = d_edge[j + 2];
        int2 e3 = d_edge[j + 3];
        float2 v0 = *(const float2*)(in + (size_t)e0.x * D + c0);
        float2 v1 = *(const float2*)(in + (size_t)e1.x * D + c0);
        float2 v2 = *(const float2*)(in + (size_t)e2.x * D + c0);
        float2 v3 = *(const float2*)(in + (size_t)e3.x * D + c0);
        float w0 = __int_as_float(e0.y), w1 = __int_as_float(e1.y);
        float w2 = __int_as_float(e2.y), w3 = __int_as_float(e3.y);
        if (APPLY) {
            v0.x = fmaxf(fmaf(v0.x, sc0, sf0), 0.f); v0.y = fmaxf(fmaf(v0.y, sc1, sf1), 0.f);
            v1.x = fmaxf(fmaf(v1.x, sc0, sf0), 0.f); v1.y = fmaxf(fmaf(v1.y, sc1, sf1), 0.f);
            v2.x = fmaxf(fmaf(v2.x, sc0, sf0), 0.f); v2.y = fmaxf(fmaf(v2.y, sc1, sf1), 0.f);
            v3.x = fmaxf(fmaf(v3.x, sc0, sf0), 0.f); v3.y = fmaxf(fmaf(v3.y, sc1, sf1), 0.f);
        }
        a0 = fmaf(w0, v0.x, a0); a1 = fmaf(w0, v0.y, a1);
        a0 = fmaf(w1, v1.x, a0); a1 = fmaf(w1, v1.y, a1);
        a0 = fmaf(w2, v2.x, a0); a1 = fmaf(w2, v2.y, a1);
        a0 = fmaf(w3, v3.x, a0); a1 = fmaf(w3, v3.y, a1);
    }
    for (; j < re; j++) {
        int2 e0 = d_edge[j];
        float w0 = __int_as_float(e0.y);
        float2 v0 = *(const float2*)(in + (size_t)e0.x * D + c0);
        if (APPLY) {
            v0.x = fmaxf(fmaf(v0.x, sc0, sf0), 0.f);
            v0.y = fmaxf(fmaf(v0.y, sc1, sf1), 0.f);
        }
        a0 = fmaf(w0, v0.x, a0);
        a1 = fmaf(w0, v0.y, a1);
    }
    *(float2*)(d_p + (size_t)node * D + c0) = make_float2(a0, a1);
}

// ------------------- fused node GEMM (FFMA2 / fp32x2 packed) -------------------
// y = p@W1 + hin@W3 + (-degw*hin)@W2 + degw*b1 + b3
// Accumulators pack NODE PAIRS in 64-bit regs; weights stored duplicated {w,w}
// in shared so the hot loop is pure LDS128 + fma.rn.f32x2 (no packing MOVs).
template <bool APPLY>
__device__ __forceinline__ void node_fetch(
    int ch, const float* __restrict__ in,
    const float* __restrict__ W1, const float* __restrict__ W2, const float* __restrict__ W3,
    int ln, bool lvalid, float dw, int slayer, int t,
    float lv[KC], float& lwA, float& lwB)
{
    int seg = ch >> 3;            // 0:W1/p  1:W3/h  2:W2/-degw*h
    int kk0 = (ch & 7) * KC;
    const float* W = (seg == 0) ? W1 : ((seg == 1) ? W3 : W2);
    int c  = t & 63;
    int ka = t >> 6;              // 0..3
    lwA = W[(kk0 + ka) * D + c];
    lwB = W[(kk0 + ka + 4) * D + c];
    if (lvalid) {
        const float* row = (seg == 0) ? (d_p + (size_t)ln * D + kk0)
                                      : (in  + (size_t)ln * D + kk0);
        float4 r0 = *(const float4*)(row);
        float4 r1 = *(const float4*)(row + 4);
        lv[0] = r0.x; lv[1] = r0.y; lv[2] = r0.z; lv[3] = r0.w;
        lv[4] = r1.x; lv[5] = r1.y; lv[6] = r1.z; lv[7] = r1.w;
        if (seg >= 1) {
            if (APPLY) {
                float4 s0 = *(const float4*)(&d_scale[slayer][kk0]);
                float4 s1 = *(const float4*)(&d_scale[slayer][kk0 + 4]);
                float4 f0 = *(const float4*)(&d_shift[slayer][kk0]);
                float4 f1 = *(const float4*)(&d_shift[slayer][kk0 + 4]);
                lv[0] = fmaxf(fmaf(lv[0], s0.x, f0.x), 0.f);
                lv[1] = fmaxf(fmaf(lv[1], s0.y, f0.y), 0.f);
                lv[2] = fmaxf(fmaf(lv[2], s0.z, f0.z), 0.f);
                lv[3] = fmaxf(fmaf(lv[3], s0.w, f0.w), 0.f);
                lv[4] = fmaxf(fmaf(lv[4], s1.x, f1.x), 0.f);
                lv[5] = fmaxf(fmaf(lv[5], s1.y, f1.y), 0.f);
                lv[6] = fmaxf(fmaf(lv[6], s1.z, f1.z), 0.f);
                lv[7] = fmaxf(fmaf(lv[7], s1.w, f1.w), 0.f);
            }
            if (seg == 2) {
                #pragma unroll
                for (int i = 0; i < KC; i++) lv[i] *= -dw;
            }
        }
    } else {
        #pragma unroll
        for (int i = 0; i < KC; i++) lv[i] = 0.f;
    }
}

template <bool APPLY>
__global__ void __launch_bounds__(256, 2) k_node(
    int insel, int slayer,
    const float* __restrict__ W1, const float* __restrict__ b1,
    const float* __restrict__ W2, const float* __restrict__ W3,
    const float* __restrict__ b3,
    int outsel, int n)
{
    __shared__ __align__(16) float  in_s[2][KC][256];
    __shared__ __align__(16) float2 w2_s[2][KC][D];   // duplicated {w,w}
    const float* __restrict__ in = nodebuf(insel);
    float* __restrict__ y = nodebuf(outsel);
    int t = threadIdx.x;
    int node0 = blockIdx.x * 256;
    int ln = node0 + t;
    bool lvalid = ln < n;
    float dw = lvalid ? d_degw[ln] : 0.f;
    int tc = t & 7;     // col group: cols [tc*8, tc*8+8)
    int tr = t >> 3;    // node group: nodes [tr*8, tr*8+8)

    unsigned long long acc2[4][8];   // [node-pair][col], fp32x2
    #pragma unroll
    for (int p = 0; p < 4; p++)
        #pragma unroll
        for (int j = 0; j < 8; j++) acc2[p][j] = 0ull;

    float lv[KC]; float lwA, lwB;
    node_fetch<APPLY>(0, in, W1, W2, W3, ln, lvalid, dw, slayer, t, lv, lwA, lwB);

    int c  = t & 63;
    int ka = t >> 6;

    const int NCH = (3 * D) / KC;   // 24
    for (int ch = 0; ch < NCH; ch++) {
        int b = ch & 1;
        w2_s[b][ka][c]     = make_float2(lwA, lwA);
        w2_s[b][ka + 4][c] = make_float2(lwB, lwB);
        #pragma unroll
        for (int i = 0; i < KC; i++) in_s[b][i][t] = lv[i];
        __syncthreads();
        if (ch + 1 < NCH)
            node_fetch<APPLY>(ch + 1, in, W1, W2, W3, ln, lvalid, dw, slayer, t, lv, lwA, lwB);
        #pragma unroll
        for (int kk = 0; kk < KC; kk++) {
            ulonglong2 ia  = *(const ulonglong2*)&in_s[b][kk][tr * 8];
            ulonglong2 ib  = *(const ulonglong2*)&in_s[b][kk][tr * 8 + 4];
            ulonglong2 w01 = *(const ulonglong2*)&w2_s[b][kk][tc * 8];
            ulonglong2 w23 = *(const ulonglong2*)&w2_s[b][kk][tc * 8 + 2];
            ulonglong2 w45 = *(const ulonglong2*)&w2_s[b][kk][tc * 8 + 4];
            ulonglong2 w67 = *(const ulonglong2*)&w2_s[b][kk][tc * 8 + 6];
            unsigned long long iv[4] = {ia.x, ia.y, ib.x, ib.y};
            unsigned long long wv[8] = {w01.x, w01.y, w23.x, w23.y,
                                        w45.x, w45.y, w67.x, w67.y};
            #pragma unroll
            for (int p = 0; p < 4; p++)
                #pragma unroll
                for (int j = 0; j < 8; j++)
                    fma2(acc2[p][j], iv[p], wv[j]);
        }
        __syncthreads();
    }

    // epilogue: + degw*b1 + b3
    float4 b1a = *(const float4*)(b1 + tc * 8);
    float4 b1b = *(const float4*)(b1 + tc * 8 + 4);
    float4 b3a = *(const float4*)(b3 + tc * 8);
    float4 b3b = *(const float4*)(b3 + tc * 8 + 4);
    float bb1[8] = {b1a.x, b1a.y, b1a.z, b1a.w, b1b.x, b1b.y, b1b.z, b1b.w};
    float bb3[8] = {b3a.x, b3a.y, b3a.z, b3a.w, b3b.x, b3b.y, b3b.z, b3b.w};
    union cvu { unsigned long long u; float2 f; };
    #pragma unroll
    for (int p = 0; p < 4; p++) {
        #pragma unroll
        for (int half = 0; half < 2; half++) {
            int node = node0 + tr * 8 + p * 2 + half;
            if (node < n) {
                float dwn = d_degw[node];
                float o[8];
                #pragma unroll
                for (int j = 0; j < 8; j++) {
                    cvu cv; cv.u = acc2[p][j];
                    float a = half ? cv.f.y : cv.f.x;
                    o[j] = a + fmaf(dwn, bb1[j], bb3[j]);
                }
                float* yp = y + (size_t)node * D + tc * 8;
                *(float4*)(yp)     = make_float4(o[0], o[1], o[2], o[3]);
                *(float4*)(yp + 4) = make_float4(o[4], o[5], o[6], o[7]);
            }
        }
    }
}

// ------------------- BN statistics (fp64, atomic-free two-stage) -------------------
__global__ void __launch_bounds__(256) k_bn_stats(int ysel, int n) {
    const float* __restrict__ y = nodebuf(ysel);
    __shared__ double sh_s[4][D];
    __shared__ double sh_q[4][D];
    int t = threadIdx.x;
    int c  = t & 63;
    int rl = t >> 6;
    int r0 = blockIdx.x * 4 + rl;
    int stride = gridDim.x * 4;
    double ls = 0.0, lq = 0.0;
    for (int r = r0; r < n; r += stride) {
        float v = y[(size_t)r * D + c];
        ls += v;
        lq += (double)v * v;
    }
    sh_s[rl][c] = ls;
    sh_q[rl][c] = lq;
    __syncthreads();
    if (t < D) {
        d_bnpart_s[blockIdx.x][t] = sh_s[0][t] + sh_s[1][t] + sh_s[2][t] + sh_s[3][t];
        d_bnpart_q[blockIdx.x][t] = sh_q[0][t] + sh_q[1][t] + sh_q[2][t] + sh_q[3][t];
    }
}

__global__ void k_bn_final(int layer, const float* __restrict__ gamma,
                           const float* __restrict__ beta, int n) {
    int c = threadIdx.x;
    if (c >= D) return;
    double s = 0.0, q = 0.0;
    for (int b = 0; b < BN_BLOCKS; b++) {
        s += d_bnpart_s[b][c];
        q += d_bnpart_q[b][c];
    }
    double m   = s / (double)n;
    double var = q / (double)n - m * m;
    if (var < 0.0) var = 0.0;
    float sc = gamma[layer * D + c] * rsqrtf((float)var + BNEPS);
    d_scale[layer][c] = sc;
    d_shift[layer][c] = beta[layer * D + c] - (float)m * sc;
}

// ------------------- graph mean pooling (BN+relu fused) -------------------
__global__ void k_pool(int ysel, int slayer, int n) {
    const float* __restrict__ y = nodebuf(ysel);
    __shared__ float red[256];
    int g = blockIdx.x;
    int s = d_goff[g], e = d_goff[g + 1];
    int t = threadIdx.x;
    int c = t & 63, rl = t >> 6;
    float sc = d_scale[slayer][c], sf = d_shift[slayer][c];
    float acc = 0.f;
    for (int r = s + rl; r < e; r += 4)
        acc += fmaxf(fmaf(y[(size_t)r * D + c], sc, sf), 0.f);
    red[t] = acc;
    __syncthreads();
    if (t < D) {
        float tot = red[t] + red[t + 64] + red[t + 128] + red[t + 192];
        float cnt = (float)(e - s);
        if (cnt < 1.f) cnt = 1.f;
        d_gpool[g * D + t] = tot / cnt;
    }
}

// ------------------- MLP head -------------------
__global__ void k_head(const float* __restrict__ Wl1, const float* __restrict__ bl1,
                       const float* __restrict__ Wl2, const float* __restrict__ bl2,
                       float* __restrict__ out) {
    __shared__ float gr[D];
    __shared__ float hid[D];
    int g = blockIdx.x;
    int t = threadIdx.x;
    gr[t] = d_gpool[g * D + t];
    __syncthreads();
    float a = bl1[t];
    #pragma unroll
    for (int k = 0; k < D; k++) a = fmaf(gr[k], Wl1[k * D + t], a);
    hid[t] = fmaxf(a, 0.f);
    __syncthreads();
    if (t < 3) {
        float o = bl2[t];
        #pragma unroll
        for (int k = 0; k < D; k++) o = fmaf(hid[k], Wl2[k * 3 + t], o);
        out[g * 3 + t] = o;
    }
}

// ------------------- launch -------------------
extern "C" void kernel_launch(void* const* d_in, const int* in_sizes, int n_in,
                              void* d_out, int out_size) {
    const float* x     = (const float*)d_in[0];
    const int*   eid   = (const int*)d_in[1];
    const float* attr  = (const float*)d_in[2];
    const int*   batch = (const int*)d_in[3];
    const float* W_emb = (const float*)d_in[4];
    const float* b_emb = (const float*)d_in[5];
    const float* W1    = (const float*)d_in[6];
    const float* b1    = (const float*)d_in[7];
    const float* W2    = (const float*)d_in[8];
    const float* W3    = (const float*)d_in[9];
    const float* b3    = (const float*)d_in[10];
    const float* gamma = (const float*)d_in[11];
    const float* beta  = (const float*)d_in[12];
    const float* Wl1   = (const float*)d_in[13];
    const float* bl1   = (const float*)d_in[14];
    const float* Wl2   = (const float*)d_in[15];
    const float* bl2   = (const float*)d_in[16];

    int N = in_sizes[0] / 4;
    int E = in_sizes[1] / 2;

    k_zero<<<(N + 255) / 256, 256>>>(N);
    k_embed<<<(N * D + 255) / 256, 256>>>(x, W_emb, b_emb, N);
    k_epass1<<<(E + 255) / 256, 256>>>(eid, attr, E);
    int nb = (N + 4095) / 4096;
    k_scan1<<<nb, 256>>>(N);
    k_scan2<<<1, 256>>>(nb);
    k_scan3<<<(N + 255) / 256, 256>>>(N);
    k_epass2<<<(E + 255) / 256, 256>>>(eid, attr, E);
    k_ghist<<<(N + 255) / 256, 256>>>(batch, N);
    k_goff<<<1, GMAX>>>();

    int EB = (N + 7) / 8;
    int NB = (N + 255) / 256;

    // layer 0
    k_edge_agg<false><<<EB, 256>>>(0, 0, N);
    k_node<false><<<NB, 256>>>(0, 0, W1, b1, W2, W3, b3, 1, N);
    k_bn_stats<<<BN_BLOCKS, 256>>>(1, N);
    k_bn_final<<<1, 64>>>(0, gamma, beta, N);

    // layer 1
    k_edge_agg<true><<<EB, 256>>>(1, 0, N);
    k_node<true><<<NB, 256>>>(1, 0, W1 + 4096, b1 + 64, W2 + 4096, W3 + 4096, b3 + 64, 2, N);
    k_bn_stats<<<BN_BLOCKS, 256>>>(2, N);
    k_bn_final<<<1, 64>>>(1, gamma, beta, N);

    // layer 2
    k_edge_agg<true><<<EB, 256>>>(2, 1, N);
    k_node<true><<<NB, 256>>>(2, 1, W1 + 8192, b1 + 128, W2 + 8192, W3 + 8192, b3 + 128, 1, N);
    k_bn_stats<<<BN_BLOCKS, 256>>>(1, N);
    k_bn_final<<<1, 64>>>(2, gamma, beta, N);

    k_pool<<<GMAX, 256>>>(1, 2, N);
    k_head<<<GMAX, 64>>>(Wl1, bl1, Wl2, bl2, (float*)d_out);
}

// round 5
// speedup vs baseline: 1.6771x; 1.6771x over previous
#include <cuda_runtime.h>
#include <math.h>

#define D 64
#define GMAX 256
#define N_MAX 100000
#define E_MAX 1200000
#define KC 8
#define BNEPS 1e-5f
#define NB_MAX 400

// ------------------- scratch (static device globals; no allocation) -------------------
__device__ __align__(16) float d_h0[(size_t)N_MAX * D];
__device__ __align__(16) float d_ya[(size_t)N_MAX * D];
__device__ __align__(16) float d_yb[(size_t)N_MAX * D];
__device__ __align__(16) float d_p [(size_t)N_MAX * D];
__device__ float d_degw[N_MAX];
__device__ int   d_cnt[N_MAX];
__device__ int   d_fill[N_MAX];
__device__ int   d_rowstart[N_MAX];
__device__ int   d_blksum[64];
__device__ __align__(16) int2 d_edge[E_MAX];   // (src, attr bits)
__device__ int   d_gcount[GMAX];
__device__ int   d_goff[GMAX + 1];
__device__ float d_bnpart_s[NB_MAX][D];
__device__ float d_bnpart_q[NB_MAX][D];
__device__ __align__(16) float d_scale[3][D];
__device__ __align__(16) float d_shift[3][D];
__device__ float d_gpool[GMAX * D];

__device__ __forceinline__ float* nodebuf(int s) {
    switch (s) {
        case 0: return d_h0;
        case 1: return d_ya;
        default: return d_yb;
    }
}

// packed fp32x2 FMA (sm_100+): per 32-bit lane d = a*b + d, IEEE fp32
__device__ __forceinline__ void fma2(unsigned long long& d,
                                     unsigned long long a,
                                     unsigned long long b) {
    asm("fma.rn.f32x2 %0, %1, %2, %0;" : "+l"(d) : "l"(a), "l"(b));
}
__device__ __forceinline__ unsigned long long dup2(float v) {
    unsigned long long d;
    int b = __float_as_int(v);
    asm("mov.b64 %0, {%1, %2};" : "=l"(d) : "r"(b), "r"(b));
    return d;
}

// ------------------- init -------------------
__global__ void k_zero(int n) {
    int i = blockIdx.x * blockDim.x + threadIdx.x;
    if (i < n) { d_cnt[i] = 0; d_fill[i] = 0; d_degw[i] = 0.f; }
    if (i < GMAX) d_gcount[i] = 0;
}

// ------------------- embedding -------------------
__global__ void k_embed(const float* __restrict__ x, const float* __restrict__ W,
                        const float* __restrict__ b, int n) {
    int i = blockIdx.x * blockDim.x + threadIdx.x;
    if (i >= n * D) return;
    int node = i >> 6, c = i & 63;
    float4 xr = *(const float4*)(x + (size_t)node * 4);
    float v = b[c];
    v = fmaf(xr.x, W[c], v);
    v = fmaf(xr.y, W[D + c], v);
    v = fmaf(xr.z, W[2 * D + c], v);
    v = fmaf(xr.w, W[3 * D + c], v);
    d_h0[i] = v;
}

// ------------------- CSR build -------------------
__global__ void k_epass1(const int* __restrict__ eid, const float* __restrict__ attr, int E) {
    int e = blockIdx.x * blockDim.x + threadIdx.x;
    if (e >= E) return;
    int dd = eid[(size_t)E + e];
    atomicAdd(&d_cnt[dd], 1);
    atomicAdd(&d_degw[dd], attr[e]);
}

__global__ void k_scan1(int n) {
    __shared__ int sh[256];
    int t = threadIdx.x;
    int base = blockIdx.x * 4096 + t * 16;
    int v[16]; int tot = 0;
    #pragma unroll
    for (int i = 0; i < 16; i++) {
        int idx = base + i;
        v[i] = (idx < n) ? d_cnt[idx] : 0;
        tot += v[i];
    }
    sh[t] = tot; __syncthreads();
    for (int off = 1; off < 256; off <<= 1) {
        int add = (t >= off) ? sh[t - off] : 0;
        __syncthreads();
        sh[t] += add;
        __syncthreads();
    }
    int run = sh[t] - tot;
    #pragma unroll
    for (int i = 0; i < 16; i++) {
        int idx = base + i;
        if (idx < n) d_rowstart[idx] = run;
        run += v[i];
    }
    if (t == 255) d_blksum[blockIdx.x] = sh[255];
}

__global__ void k_scan2(int nb) {
    __shared__ int sh[256];
    int t = threadIdx.x;
    int v = (t < nb) ? d_blksum[t] : 0;
    sh[t] = v; __syncthreads();
    for (int off = 1; off < 256; off <<= 1) {
        int add = (t >= off) ? sh[t - off] : 0;
        __syncthreads();
        sh[t] += add;
        __syncthreads();
    }
    if (t < nb) d_blksum[t] = sh[t] - v;
}

__global__ void k_scan3(int n) {
    int i = blockIdx.x * blockDim.x + threadIdx.x;
    if (i < n) d_rowstart[i] += d_blksum[i >> 12];
}

__global__ void k_epass2(const int* __restrict__ eid, const float* __restrict__ attr, int E) {
    int e = blockIdx.x * blockDim.x + threadIdx.x;
    if (e >= E) return;
    int s  = eid[e];
    int dd = eid[(size_t)E + e];
    int pos = d_rowstart[dd] + atomicAdd(&d_fill[dd], 1);
    d_edge[pos] = make_int2(s, __float_as_int(attr[e]));
}

// ------------------- graph histogram + offsets -------------------
__global__ void k_ghist(const int* __restrict__ batch, int n) {
    int i = blockIdx.x * blockDim.x + threadIdx.x;
    if (i < n) atomicAdd(&d_gcount[batch[i]], 1);
}

__global__ void k_goff() {
    __shared__ int sh[GMAX];
    int t = threadIdx.x;
    int v = d_gcount[t];
    sh[t] = v; __syncthreads();
    for (int off = 1; off < GMAX; off <<= 1) {
        int add = (t >= off) ? sh[t - off] : 0;
        __syncthreads();
        sh[t] += add;
        __syncthreads();
    }
    d_goff[t + 1] = sh[t];
    if (t == 0) d_goff[0] = 0;
}

// ------------------- edge aggregation: p[i] = sum attr_e * hin[src_e] -------------------
template <bool APPLY>
__global__ void k_edge_agg(int insel, int slayer, int n) {
    int node = blockIdx.x * 8 + (threadIdx.x >> 5);
    if (node >= n) return;
    const float* __restrict__ in = nodebuf(insel);
    int lane = threadIdx.x & 31;
    int c0 = lane * 2;
    float sc0 = 1.f, sc1 = 1.f, sf0 = 0.f, sf1 = 0.f;
    if (APPLY) {
        sc0 = d_scale[slayer][c0];     sc1 = d_scale[slayer][c0 + 1];
        sf0 = d_shift[slayer][c0];     sf1 = d_shift[slayer][c0 + 1];
    }
    int rs = d_rowstart[node];
    int re = rs + d_cnt[node];
    float a0 = 0.f, a1 = 0.f;
    int j = rs;
    for (; j + 4 <= re; j += 4) {
        int2 e0 = d_edge[j];
        int2 e1 = d_edge[j + 1];
        int2 e2 = d_edge[j + 2];
        int2 e3 = d_edge[j + 3];
        float2 v0 = *(const float2*)(in + (size_t)e0.x * D + c0);
        float2 v1 = *(const float2*)(in + (size_t)e1.x * D + c0);
        float2 v2 = *(const float2*)(in + (size_t)e2.x * D + c0);
        float2 v3 = *(const float2*)(in + (size_t)e3.x * D + c0);
        float w0 = __int_as_float(e0.y), w1 = __int_as_float(e1.y);
        float w2 = __int_as_float(e2.y), w3 = __int_as_float(e3.y);
        if (APPLY) {
            v0.x = fmaxf(fmaf(v0.x, sc0, sf0), 0.f); v0.y = fmaxf(fmaf(v0.y, sc1, sf1), 0.f);
            v1.x = fmaxf(fmaf(v1.x, sc0, sf0), 0.f); v1.y = fmaxf(fmaf(v1.y, sc1, sf1), 0.f);
            v2.x = fmaxf(fmaf(v2.x, sc0, sf0), 0.f); v2.y = fmaxf(fmaf(v2.y, sc1, sf1), 0.f);
            v3.x = fmaxf(fmaf(v3.x, sc0, sf0), 0.f); v3.y = fmaxf(fmaf(v3.y, sc1, sf1), 0.f);
        }
        a0 = fmaf(w0, v0.x, a0); a1 = fmaf(w0, v0.y, a1);
        a0 = fmaf(w1, v1.x, a0); a1 = fmaf(w1, v1.y, a1);
        a0 = fmaf(w2, v2.x, a0); a1 = fmaf(w2, v2.y, a1);
        a0 = fmaf(w3, v3.x, a0); a1 = fmaf(w3, v3.y, a1);
    }
    for (; j < re; j++) {
        int2 e0 = d_edge[j];
        float w0 = __int_as_float(e0.y);
        float2 v0 = *(const float2*)(in + (size_t)e0.x * D + c0);
        if (APPLY) {
            v0.x = fmaxf(fmaf(v0.x, sc0, sf0), 0.f);
            v0.y = fmaxf(fmaf(v0.y, sc1, sf1), 0.f);
        }
        a0 = fmaf(w0, v0.x, a0);
        a1 = fmaf(w0, v0.y, a1);
    }
    *(float2*)(d_p + (size_t)node * D + c0) = make_float2(a0, a1);
}

// ------------------- fused node GEMM (f32x2 over column pairs) + fused BN stats ----------
// y = p@W1 + hin@W3 + (-degw*hin)@W2 + degw*b1 + b3
// Shared layout identical to R3 (no duplication). Column pairs come free from
// w_s via LDS128; the node scalar is duplicated in-register (mov.b64 {v,v}).
template <bool APPLY>
__device__ __forceinline__ void node_fetch(
    int ch, const float* __restrict__ in,
    const float* __restrict__ W1, const float* __restrict__ W2, const float* __restrict__ W3,
    int ln, bool lvalid, float dw, int slayer,
    float lv[KC], float& lw0, float& lw1)
{
    int seg = ch >> 3;
    int kk0 = (ch & 7) * KC;
    const float* W = (seg == 0) ? W1 : ((seg == 1) ? W3 : W2);
    float2 wv = *(const float2*)(W + kk0 * D + threadIdx.x * 2);
    lw0 = wv.x; lw1 = wv.y;
    if (lvalid) {
        const float* row = (seg == 0) ? (d_p + (size_t)ln * D + kk0)
                                      : (in  + (size_t)ln * D + kk0);
        float4 r0 = *(const float4*)(row);
        float4 r1 = *(const float4*)(row + 4);
        lv[0] = r0.x; lv[1] = r0.y; lv[2] = r0.z; lv[3] = r0.w;
        lv[4] = r1.x; lv[5] = r1.y; lv[6] = r1.z; lv[7] = r1.w;
        if (seg >= 1) {
            if (APPLY) {
                float4 s0 = *(const float4*)(&d_scale[slayer][kk0]);
                float4 s1 = *(const float4*)(&d_scale[slayer][kk0 + 4]);
                float4 f0 = *(const float4*)(&d_shift[slayer][kk0]);
                float4 f1 = *(const float4*)(&d_shift[slayer][kk0 + 4]);
                lv[0] = fmaxf(fmaf(lv[0], s0.x, f0.x), 0.f);
                lv[1] = fmaxf(fmaf(lv[1], s0.y, f0.y), 0.f);
                lv[2] = fmaxf(fmaf(lv[2], s0.z, f0.z), 0.f);
                lv[3] = fmaxf(fmaf(lv[3], s0.w, f0.w), 0.f);
                lv[4] = fmaxf(fmaf(lv[4], s1.x, f1.x), 0.f);
                lv[5] = fmaxf(fmaf(lv[5], s1.y, f1.y), 0.f);
                lv[6] = fmaxf(fmaf(lv[6], s1.z, f1.z), 0.f);
                lv[7] = fmaxf(fmaf(lv[7], s1.w, f1.w), 0.f);
            }
            if (seg == 2) {
                #pragma unroll
                for (int i = 0; i < KC; i++) lv[i] *= -dw;
            }
        }
    } else {
        #pragma unroll
        for (int i = 0; i < KC; i++) lv[i] = 0.f;
    }
}

template <bool APPLY>
__global__ void __launch_bounds__(256) k_node(
    int insel, int slayer,
    const float* __restrict__ W1, const float* __restrict__ b1,
    const float* __restrict__ W2, const float* __restrict__ W3,
    const float* __restrict__ b3,
    int outsel, int n)
{
    __shared__ __align__(16) float in_s[2][KC][256];
    __shared__ __align__(16) float w_s[2][KC][D];
    __shared__ __align__(16) float bns[32][D + 1];
    __shared__ __align__(16) float bnq[32][D + 1];
    const float* __restrict__ in = nodebuf(insel);
    float* __restrict__ y = nodebuf(outsel);
    int t = threadIdx.x;
    int node0 = blockIdx.x * 256;
    int ln = node0 + t;
    bool lvalid = ln < n;
    float dw = lvalid ? d_degw[ln] : 0.f;
    int tc = t & 7;
    int tr = t >> 3;

    unsigned long long acc2[8][4];   // [node][col-pair]
    #pragma unroll
    for (int i = 0; i < 8; i++)
        #pragma unroll
        for (int j = 0; j < 4; j++) acc2[i][j] = 0ull;

    float lv[KC]; float lw0, lw1;
    node_fetch<APPLY>(0, in, W1, W2, W3, ln, lvalid, dw, slayer, lv, lw0, lw1);

    const int NCH = (3 * D) / KC;   // 24
    for (int ch = 0; ch < NCH; ch++) {
        int b = ch & 1;
        *((float2*)(&w_s[b][0][0]) + t) = make_float2(lw0, lw1);
        #pragma unroll
        for (int i = 0; i < KC; i++) in_s[b][i][t] = lv[i];
        __syncthreads();
        if (ch + 1 < NCH)
            node_fetch<APPLY>(ch + 1, in, W1, W2, W3, ln, lvalid, dw, slayer, lv, lw0, lw1);
        #pragma unroll
        for (int kk = 0; kk < KC; kk++) {
            float4 ia = *(const float4*)&in_s[b][kk][tr * 8];
            float4 ib = *(const float4*)&in_s[b][kk][tr * 8 + 4];
            ulonglong2 wa = *(const ulonglong2*)&w_s[b][kk][tc * 8];
            ulonglong2 wb = *(const ulonglong2*)&w_s[b][kk][tc * 8 + 4];
            unsigned long long wv[4] = {wa.x, wa.y, wb.x, wb.y};
            unsigned long long dv[8];
            dv[0] = dup2(ia.x); dv[1] = dup2(ia.y); dv[2] = dup2(ia.z); dv[3] = dup2(ia.w);
            dv[4] = dup2(ib.x); dv[5] = dup2(ib.y); dv[6] = dup2(ib.z); dv[7] = dup2(ib.w);
            #pragma unroll
            for (int i = 0; i < 8; i++)
                #pragma unroll
                for (int j = 0; j < 4; j++)
                    fma2(acc2[i][j], dv[i], wv[j]);
        }
        __syncthreads();
    }

    // epilogue: + degw*b1 + b3, write y, accumulate BN partials
    float4 b1a = *(const float4*)(b1 + tc * 8);
    float4 b1b = *(const float4*)(b1 + tc * 8 + 4);
    float4 b3a = *(const float4*)(b3 + tc * 8);
    float4 b3b = *(const float4*)(b3 + tc * 8 + 4);
    float bb1[8] = {b1a.x, b1a.y, b1a.z, b1a.w, b1b.x, b1b.y, b1b.z, b1b.w};
    float bb3[8] = {b3a.x, b3a.y, b3a.z, b3a.w, b3b.x, b3b.y, b3b.z, b3b.w};
    float s_acc[8], q_acc[8];
    #pragma unroll
    for (int j = 0; j < 8; j++) { s_acc[j] = 0.f; q_acc[j] = 0.f; }
    union cvu { unsigned long long u; float2 f; };
    #pragma unroll
    for (int i = 0; i < 8; i++) {
        int node = node0 + tr * 8 + i;
        if (node < n) {
            float dwn = d_degw[node];
            float o[8];
            #pragma unroll
            for (int jp = 0; jp < 4; jp++) {
                cvu cv; cv.u = acc2[i][jp];
                o[jp * 2]     = cv.f.x + fmaf(dwn, bb1[jp * 2],     bb3[jp * 2]);
                o[jp * 2 + 1] = cv.f.y + fmaf(dwn, bb1[jp * 2 + 1], bb3[jp * 2 + 1]);
            }
            #pragma unroll
            for (int j = 0; j < 8; j++) {
                s_acc[j] += o[j];
                q_acc[j] = fmaf(o[j], o[j], q_acc[j]);
            }
            float* yp = y + (size_t)node * D + tc * 8;
            *(float4*)(yp)     = make_float4(o[0], o[1], o[2], o[3]);
            *(float4*)(yp + 4) = make_float4(o[4], o[5], o[6], o[7]);
        }
    }
    #pragma unroll
    for (int j = 0; j < 8; j++) {
        bns[tr][tc * 8 + j] = s_acc[j];
        bnq[tr][tc * 8 + j] = q_acc[j];
    }
    __syncthreads();
    if (t < D) {
        float s = 0.f, q = 0.f;
        #pragma unroll
        for (int r = 0; r < 32; r++) { s += bns[r][t]; q += bnq[r][t]; }
        d_bnpart_s[blockIdx.x][t] = s;
        d_bnpart_q[blockIdx.x][t] = q;
    }
}

// ------------------- BN finalize (fp64 over per-block fp32 partials) -------------------
__global__ void k_bn_final(int layer, const float* __restrict__ gamma,
                           const float* __restrict__ beta, int n, int nblocks) {
    int c = threadIdx.x;
    if (c >= D) return;
    double s = 0.0, q = 0.0;
    for (int b = 0; b < nblocks; b++) {
        s += (double)d_bnpart_s[b][c];
        q += (double)d_bnpart_q[b][c];
    }
    double m   = s / (double)n;
    double var = q / (double)n - m * m;
    if (var < 0.0) var = 0.0;
    float sc = gamma[layer * D + c] * rsqrtf((float)var + BNEPS);
    d_scale[layer][c] = sc;
    d_shift[layer][c] = beta[layer * D + c] - (float)m * sc;
}

// ------------------- graph mean pooling (BN+relu fused) -------------------
__global__ void k_pool(int ysel, int slayer, int n) {
    const float* __restrict__ y = nodebuf(ysel);
    __shared__ float red[256];
    int g = blockIdx.x;
    int s = d_goff[g], e = d_goff[g + 1];
    int t = threadIdx.x;
    int c = t & 63, rl = t >> 6;
    float sc = d_scale[slayer][c], sf = d_shift[slayer][c];
    float acc = 0.f;
    for (int r = s + rl; r < e; r += 4)
        acc += fmaxf(fmaf(y[(size_t)r * D + c], sc, sf), 0.f);
    red[t] = acc;
    __syncthreads();
    if (t < D) {
        float tot = red[t] + red[t + 64] + red[t + 128] + red[t + 192];
        float cnt = (float)(e - s);
        if (cnt < 1.f) cnt = 1.f;
        d_gpool[g * D + t] = tot / cnt;
    }
}

// ------------------- MLP head -------------------
__global__ void k_head(const float* __restrict__ Wl1, const float* __restrict__ bl1,
                       const float* __restrict__ Wl2, const float* __restrict__ bl2,
                       float* __restrict__ out) {
    __shared__ float gr[D];
    __shared__ float hid[D];
    int g = blockIdx.x;
    int t = threadIdx.x;
    gr[t] = d_gpool[g * D + t];
    __syncthreads();
    float a = bl1[t];
    #pragma unroll
    for (int k = 0; k < D; k++) a = fmaf(gr[k], Wl1[k * D + t], a);
    hid[t] = fmaxf(a, 0.f);
    __syncthreads();
    if (t < 3) {
        float o = bl2[t];
        #pragma unroll
        for (int k = 0; k < D; k++) o = fmaf(hid[k], Wl2[k * 3 + t], o);
        out[g * 3 + t] = o;
    }
}

// ------------------- launch -------------------
extern "C" void kernel_launch(void* const* d_in, const int* in_sizes, int n_in,
                              void* d_out, int out_size) {
    const float* x     = (const float*)d_in[0];
    const int*   eid   = (const int*)d_in[1];
    const float* attr  = (const float*)d_in[2];
    const int*   batch = (const int*)d_in[3];
    const float* W_emb = (const float*)d_in[4];
    const float* b_emb = (const float*)d_in[5];
    const float* W1    = (const float*)d_in[6];
    const float* b1    = (const float*)d_in[7];
    const float* W2    = (const float*)d_in[8];
    const float* W3    = (const float*)d_in[9];
    const float* b3    = (const float*)d_in[10];
    const float* gamma = (const float*)d_in[11];
    const float* beta  = (const float*)d_in[12];
    const float* Wl1   = (const float*)d_in[13];
    const float* bl1   = (const float*)d_in[14];
    const float* Wl2   = (const float*)d_in[15];
    const float* bl2   = (const float*)d_in[16];

    int N = in_sizes[0] / 4;
    int E = in_sizes[1] / 2;

    k_zero<<<(N + 255) / 256, 256>>>(N);
    k_embed<<<(N * D + 255) / 256, 256>>>(x, W_emb, b_emb, N);
    k_epass1<<<(E + 255) / 256, 256>>>(eid, attr, E);
    int nb = (N + 4095) / 4096;
    k_scan1<<<nb, 256>>>(N);
    k_scan2<<<1, 256>>>(nb);
    k_scan3<<<(N + 255) / 256, 256>>>(N);
    k_epass2<<<(E + 255) / 256, 256>>>(eid, attr, E);
    k_ghist<<<(N + 255) / 256, 256>>>(batch, N);
    k_goff<<<1, GMAX>>>();

    int EB = (N + 7) / 8;
    int NB = (N + 255) / 256;

    // layer 0
    k_edge_agg<false><<<EB, 256>>>(0, 0, N);
    k_node<false><<<NB, 256>>>(0, 0, W1, b1, W2, W3, b3, 1, N);
    k_bn_final<<<1, 64>>>(0, gamma, beta, N, NB);

    // layer 1
    k_edge_agg<true><<<EB, 256>>>(1, 0, N);
    k_node<true><<<NB, 256>>>(1, 0, W1 + 4096, b1 + 64, W2 + 4096, W3 + 4096, b3 + 64, 2, N);
    k_bn_final<<<1, 64>>>(1, gamma, beta, N, NB);

    // layer 2
    k_edge_agg<true><<<EB, 256>>>(2, 1, N);
    k_node<true><<<NB, 256>>>(2, 1, W1 + 8192, b1 + 128, W2 + 8192, W3 + 8192, b3 + 128, 1, N);
    k_bn_final<<<1, 64>>>(2, gamma, beta, N, NB);

    k_pool<<<GMAX, 256>>>(1, 2, N);
    k_head<<<GMAX, 64>>>(Wl1, bl1, Wl2, bl2, (float*)d_out);
}